// round 13
// baseline (speedup 1.0000x reference)
#include <cuda_runtime.h>

#define NN    4
#define CC    20
#define HH    64
#define WWID  2048
#define KHW   5
#define PLANE (HH * WWID)     // 131072

#define TPB   128
#define TILE  256             // output px per block, 2 px/thread
#define COLS  264             // staged cols: ww = w0-4 .. w0+259
#define NV4   (COLS / 4)      // 66 float4 per row
#define CH_PER_G   4
#define NGROUPS    (CC / CH_PER_G)           // 5
#define STAGE_FLTS (CH_PER_G * KHW * COLS)   // 5280 floats per stage
#define NSTAGE     2                          // 42240 B total
#define HSLOTS     (2 * KHW * NV4)           // 660 slots per 2-channel half
#define SL_FULL    5                          // 128*5 = 640
#define SL_REM     (HSLOTS - TPB * SL_FULL)   // 20 (threads 0..19)
#define HALF_S     (2 * KHW * COLS)          // smem stride between halves
#define HALF_G     (2 * PLANE)               // gmem stride between halves

__device__ __forceinline__ void cp_async16(void* smem, const void* gmem)
{
    unsigned saddr = (unsigned)__cvta_generic_to_shared(smem);
    asm volatile("cp.async.cg.shared.global [%0], [%1], 16;\n"
                 :: "r"(saddr), "l"(gmem));
}
__device__ __forceinline__ void cp_commit()
{
    asm volatile("cp.async.commit_group;\n" ::: "memory");
}
template <int N>
__device__ __forceinline__ void cp_wait()
{
    asm volatile("cp.async.wait_group %0;\n" :: "n"(N) : "memory");
}

__global__ __launch_bounds__(TPB, 5)
void lcxyz_kernel(const float* __restrict__ xyz,
                  const float* __restrict__ softmax,
                  const void* __restrict__ mask,
                  float* __restrict__ out)
{
    __shared__ float ring[NSTAGE * STAGE_FLTS];
    __shared__ int   sh_mode;

    const int t  = threadIdx.x;
    const int w0 = blockIdx.x * TILE;
    const int h  = blockIdx.y;
    const int n  = blockIdx.z;

    // ---- mask dtype detection (warp 0): 0=u8, 1=i32, 2=f32 ----
    if (t < 32) {
        const unsigned* m = (const unsigned*)mask;
        unsigned w1 = m[t], w2 = m[t + 32];
        bool i32ok = (w1 <= 1u) && (w2 <= 1u);
        bool f32ok = (w1 == 0u || w1 == 0x3F800000u) &&
                     (w2 == 0u || w2 == 0x3F800000u);
        unsigned bi = __ballot_sync(0xFFFFFFFFu, i32ok);
        unsigned bf = __ballot_sync(0xFFFFFFFFu, f32ok);
        if (t == 0) sh_mode = (bi == 0xFFFFFFFFu) ? 1 : ((bf == 0xFFFFFFFFu) ? 2 : 0);
    }

    int hrow[KHW];
#pragma unroll
    for (int r = 0; r < KHW; ++r)
        hrow[r] = min(max(h + r - 2, 0), HH - 1);

    const float* sm_base = softmax + (size_t)(n * CC) * PLANE;

    // ---- Precompute 2-channel-half staging slots (reused twice per group) ----
    unsigned soff[SL_FULL], goff[SL_FULL];
    unsigned soffX = 0, goffX = 0;
    const bool hasX = (t < SL_REM);
#pragma unroll
    for (int k = 0; k <= SL_FULL; ++k) {
        int j = (k < SL_FULL) ? (t + TPB * k) : (TPB * SL_FULL + t);
        int ch  = j / (KHW * NV4);            // 0 or 1
        int rem = j - ch * (KHW * NV4);
        int rr  = rem / NV4;
        int i   = rem - rr * NV4;
        unsigned so = ch * (KHW * COLS) + rr * COLS + 4 * i;
        int gidx = hrow[rr] * WWID + (w0 - 4) + 4 * i;
        gidx = min(max(gidx, 0), PLANE - 4);  // edge garbage killed by gm=0
        unsigned go = ch * PLANE + gidx;
        if (k < SL_FULL) { soff[k] = so; goff[k] = go; }
        else             { soffX   = so; goffX   = go; }
    }

    // ---- Prologue: prefetch group 0 (4 channels) into stage 0 ----
#pragma unroll
    for (int half = 0; half < 2; ++half) {
        float* sb = ring + half * HALF_S;
        const float* gb = sm_base + (size_t)half * HALF_G;
#pragma unroll
        for (int k = 0; k < SL_FULL; ++k)
            cp_async16(sb + soff[k], gb + goff[k]);
        if (hasX) cp_async16(sb + soffX, gb + goffX);
    }
    cp_commit();

    __syncthreads();    // sh_mode visible
    const int mmode = sh_mode;

    // ---- Phase 1: masked Gaussian weights for 2 adjacent pixels ----
    const int wa = w0 + 2 * t;
    const int cc = 2 * t + 4;

    const float* Xx = xyz + (size_t)n * 3 * PLANE;
    const float* Xy = Xx + PLANE;
    const float* Xz = Xy + PLANE;
    const size_t mbase = (size_t)n * PLANE;
    const unsigned char* mk_u8  = (const unsigned char*)mask + mbase;
    const int*           mk_i32 = (const int*)mask + mbase;
    const float*         mk_f32 = (const float*)mask + mbase;

    const float cx0 = Xx[h * WWID + wa],     cy0 = Xy[h * WWID + wa],     cz0 = Xz[h * WWID + wa];
    const float cx1 = Xx[h * WWID + wa + 1], cy1 = Xy[h * WWID + wa + 1], cz1 = Xz[h * WWID + wa + 1];

    float gm0[25], gm1[25];
#pragma unroll
    for (int dy = 0; dy < KHW; ++dy) {
        const int hc  = hrow[dy];
        const int hh  = h + dy - 2;
        const bool hok = (hh >= 0) && (hh < HH);
        float m[6], nx[6], ny[6], nz[6];
#pragma unroll
        for (int j = 0; j < 6; ++j) {
            int wraw = wa + j - 2;
            int ww = min(max(wraw, 0), WWID - 1);
            int idx = hc * WWID + ww;
            nx[j] = Xx[idx];  ny[j] = Xy[idx];  nz[j] = Xz[idx];
            bool ok = hok && (wraw >= 0) && (wraw < WWID);
            float mv = 0.0f;
            if (ok) {
                if (mmode == 1)      mv = (float)mk_i32[idx];
                else if (mmode == 2) mv = mk_f32[idx];
                else                 mv = (float)mk_u8[idx];
            }
            m[j] = mv;
        }
#pragma unroll
        for (int dx = 0; dx < KHW; ++dx) {
            float ax = nx[dx] - cx0, ay = ny[dx] - cy0, az = nz[dx] - cz0;
            float d2a = fmaf(ax, ax, fmaf(ay, ay, az * az));
            gm0[dy*5+dx] = m[dx] * __expf(-0.5f * d2a);
            float bx = nx[dx+1] - cx1, by = ny[dx+1] - cy1, bz = nz[dx+1] - cz1;
            float d2b = fmaf(bx, bx, fmaf(by, by, bz * bz));
            gm1[dy*5+dx] = m[dx+1] * __expf(-0.5f * d2b);
        }
    }

    // ---- Phase 2: 5 groups of 4 channels, safe 2-stage ping-pong ----
    // Order per iter: wait(g landed) -> barrier (readers of the other stage,
    // from iter g-1, are done) -> prefetch g+1 into other stage -> compute g.
    float* outp = out + ((size_t)(n * CC) * HH + h) * WWID + wa;

    for (int g = 0; g < NGROUPS; ++g) {
        cp_wait<0>();            // only group g's prefetch can be outstanding
        __syncthreads();

        if (g + 1 < NGROUPS) {
            float* buf = ring + ((g + 1) & 1) * STAGE_FLTS;
            const float* gb = sm_base + (size_t)(g + 1) * (CH_PER_G * PLANE);
#pragma unroll
            for (int half = 0; half < 2; ++half) {
                float* sb = buf + half * HALF_S;
                const float* gbh = gb + (size_t)half * HALF_G;
#pragma unroll
                for (int k = 0; k < SL_FULL; ++k)
                    cp_async16(sb + soff[k], gbh + goff[k]);
                if (hasX) cp_async16(sb + soffX, gbh + goffX);
            }
            cp_commit();
        }

        const float* B = ring + (g & 1) * STAGE_FLTS;
        // channels in interleaved pairs: 2 independent LDS/FMA streams
#pragma unroll
        for (int cp2 = 0; cp2 < CH_PER_G; cp2 += 2) {
            const float* BcA = B + (cp2 + 0) * (KHW * COLS) + (cc - 2);
            const float* BcB = B + (cp2 + 1) * (KHW * COLS) + (cc - 2);
            float A0e = 0.f, A0o = 0.f, A1e = 0.f, A1o = 0.f;
            float B0e = 0.f, B0o = 0.f, B1e = 0.f, B1o = 0.f;
#pragma unroll
            for (int dy = 0; dy < KHW; ++dy) {
                const float* ra = BcA + dy * COLS;
                const float* rb = BcB + dy * COLS;
                float2 a01 = *(const float2*)(ra);
                float2 b01 = *(const float2*)(rb);
                float2 a23 = *(const float2*)(ra + 2);
                float2 b23 = *(const float2*)(rb + 2);
                float2 a45 = *(const float2*)(ra + 4);
                float2 b45 = *(const float2*)(rb + 4);
                const float w0_ = gm0[dy*5+0], w1_ = gm0[dy*5+1], w2_ = gm0[dy*5+2],
                            w3_ = gm0[dy*5+3], w4_ = gm0[dy*5+4];
                const float v0_ = gm1[dy*5+0], v1_ = gm1[dy*5+1], v2_ = gm1[dy*5+2],
                            v3_ = gm1[dy*5+3], v4_ = gm1[dy*5+4];
                A0e = fmaf(w0_, a01.x, A0e);  B0e = fmaf(w0_, b01.x, B0e);
                A1e = fmaf(v0_, a01.y, A1e);  B1e = fmaf(v0_, b01.y, B1e);
                A0o = fmaf(w1_, a01.y, A0o);  B0o = fmaf(w1_, b01.y, B0o);
                A1o = fmaf(v1_, a23.x, A1o);  B1o = fmaf(v1_, b23.x, B1o);
                A0e = fmaf(w2_, a23.x, A0e);  B0e = fmaf(w2_, b23.x, B0e);
                A1e = fmaf(v2_, a23.y, A1e);  B1e = fmaf(v2_, b23.y, B1e);
                A0o = fmaf(w3_, a23.y, A0o);  B0o = fmaf(w3_, b23.y, B0o);
                A1o = fmaf(v3_, a45.x, A1o);  B1o = fmaf(v3_, b45.x, B1o);
                A0e = fmaf(w4_, a45.x, A0e);  B0e = fmaf(w4_, b45.x, B0e);
                A1e = fmaf(v4_, a45.y, A1e);  B1e = fmaf(v4_, b45.y, B1e);
            }
            const int chA = g * CH_PER_G + cp2;
            *(float2*)(outp + (size_t)(chA + 0) * PLANE) = make_float2(A0e + A0o, A1e + A1o);
            *(float2*)(outp + (size_t)(chA + 1) * PLANE) = make_float2(B0e + B0o, B1e + B1o);
        }
    }
}

extern "C" void kernel_launch(void* const* d_in, const int* in_sizes, int n_in,
                              void* d_out, int out_size)
{
    const float* xyz     = (const float*)d_in[0];
    const float* softmax = (const float*)d_in[1];
    const void*  mask    = d_in[2];
    float*       out     = (float*)d_out;

    dim3 grid(WWID / TILE, HH, NN);   // (8, 64, 4) = 2048 blocks
    dim3 block(TPB);
    lcxyz_kernel<<<grid, block>>>(xyz, softmax, mask, out);
}

// round 14
// speedup vs baseline: 1.1096x; 1.1096x over previous
#include <cuda_runtime.h>

#define NN    4
#define CC    20
#define HH    64
#define WWID  2048
#define KHW   5
#define PLANE (HH * WWID)     // 131072

#define TPB   128
#define TILE  256             // output px per block, 2 px/thread
#define COLS  264             // staged cols: ww = w0-4 .. w0+259
#define NV4   (COLS / 4)      // 66 float4 per row
#define CH_PER_G   2
#define NGROUPS    (CC / CH_PER_G)           // 10
#define STAGE_FLTS (CH_PER_G * KHW * COLS)   // 2640 floats per ring stage
#define NSTAGE     4                          // 42240 B total
#define SLOTS      (CH_PER_G * KHW * NV4)    // 660 float4 copies per group
#define SLOTS_FULL 5                          // 128*5 = 640
#define SLOTS_REM  (SLOTS - TPB * SLOTS_FULL) // 20 (threads 0..19)

__device__ __forceinline__ void cp_async16(void* smem, const void* gmem)
{
    unsigned saddr = (unsigned)__cvta_generic_to_shared(smem);
    asm volatile("cp.async.cg.shared.global [%0], [%1], 16;\n"
                 :: "r"(saddr), "l"(gmem));
}
__device__ __forceinline__ void cp_commit()
{
    asm volatile("cp.async.commit_group;\n" ::: "memory");
}
template <int N>
__device__ __forceinline__ void cp_wait()
{
    asm volatile("cp.async.wait_group %0;\n" :: "n"(N) : "memory");
}

__global__ __launch_bounds__(TPB, 5)
void lcxyz_kernel(const float* __restrict__ xyz,
                  const float* __restrict__ softmax,
                  const void* __restrict__ mask,
                  float* __restrict__ out)
{
    __shared__ float ring[NSTAGE * STAGE_FLTS];
    __shared__ int   sh_mode;

    const int t  = threadIdx.x;
    const int w0 = blockIdx.x * TILE;
    const int h  = blockIdx.y;
    const int n  = blockIdx.z;

    // ---- mask dtype detection (warp 0): 0=u8, 1=i32, 2=f32 ----
    if (t < 32) {
        const unsigned* m = (const unsigned*)mask;
        unsigned w1 = m[t], w2 = m[t + 32];
        bool i32ok = (w1 <= 1u) && (w2 <= 1u);
        bool f32ok = (w1 == 0u || w1 == 0x3F800000u) &&
                     (w2 == 0u || w2 == 0x3F800000u);
        unsigned bi = __ballot_sync(0xFFFFFFFFu, i32ok);
        unsigned bf = __ballot_sync(0xFFFFFFFFu, f32ok);
        if (t == 0) sh_mode = (bi == 0xFFFFFFFFu) ? 1 : ((bf == 0xFFFFFFFFu) ? 2 : 0);
    }

    int hrow[KHW];
#pragma unroll
    for (int r = 0; r < KHW; ++r)
        hrow[r] = min(max(h + r - 2, 0), HH - 1);

    const float* sm_base = softmax + (size_t)(n * CC) * PLANE;

    // ---- Precompute staging slots: 5 per thread + 1 extra for t<20 ----
    unsigned soff[SLOTS_FULL], goff[SLOTS_FULL];
    unsigned soffX = 0, goffX = 0;
    const bool hasX = (t < SLOTS_REM);
#pragma unroll
    for (int k = 0; k <= SLOTS_FULL; ++k) {
        int j = (k < SLOTS_FULL) ? (t + TPB * k) : (TPB * SLOTS_FULL + t);
        int ch  = j / (KHW * NV4);
        int rem = j - ch * (KHW * NV4);
        int rr  = rem / NV4;
        int i   = rem - rr * NV4;
        unsigned so = ch * (KHW * COLS) + rr * COLS + 4 * i;
        int gidx = hrow[rr] * WWID + (w0 - 4) + 4 * i;
        gidx = min(max(gidx, 0), PLANE - 4);     // edge garbage killed by gm=0
        unsigned go = ch * PLANE + gidx;
        if (k < SLOTS_FULL) { soff[k] = so; goff[k] = go; }
        else                { soffX   = so; goffX   = go; }
    }

    // ---- Prologue: prefetch groups 0 (stage 0) and 1 (stage 1) ----
#pragma unroll
    for (int k = 0; k < SLOTS_FULL; ++k)
        cp_async16(ring + soff[k], sm_base + goff[k]);
    if (hasX) cp_async16(ring + soffX, sm_base + goffX);
    cp_commit();
#pragma unroll
    for (int k = 0; k < SLOTS_FULL; ++k)
        cp_async16(ring + STAGE_FLTS + soff[k], sm_base + CH_PER_G * PLANE + goff[k]);
    if (hasX) cp_async16(ring + STAGE_FLTS + soffX, sm_base + CH_PER_G * PLANE + goffX);
    cp_commit();

    __syncthreads();    // sh_mode visible
    const int mmode = sh_mode;

    // ---- Phase 1: masked Gaussian weights for 2 adjacent pixels ----
    const int wa = w0 + 2 * t;
    const int cc = 2 * t + 4;

    const float* Xx = xyz + (size_t)n * 3 * PLANE;
    const float* Xy = Xx + PLANE;
    const float* Xz = Xy + PLANE;
    const size_t mbase = (size_t)n * PLANE;
    const unsigned char* mk_u8  = (const unsigned char*)mask + mbase;
    const int*           mk_i32 = (const int*)mask + mbase;
    const float*         mk_f32 = (const float*)mask + mbase;

    const float cx0 = Xx[h * WWID + wa],     cy0 = Xy[h * WWID + wa],     cz0 = Xz[h * WWID + wa];
    const float cx1 = Xx[h * WWID + wa + 1], cy1 = Xy[h * WWID + wa + 1], cz1 = Xz[h * WWID + wa + 1];

    float gm0[25], gm1[25];
#pragma unroll
    for (int dy = 0; dy < KHW; ++dy) {
        const int hc  = hrow[dy];
        const int hh  = h + dy - 2;
        const bool hok = (hh >= 0) && (hh < HH);
        float m[6], nx[6], ny[6], nz[6];
#pragma unroll
        for (int j = 0; j < 6; ++j) {
            int wraw = wa + j - 2;
            int ww = min(max(wraw, 0), WWID - 1);
            int idx = hc * WWID + ww;
            nx[j] = Xx[idx];  ny[j] = Xy[idx];  nz[j] = Xz[idx];
            bool ok = hok && (wraw >= 0) && (wraw < WWID);
            float mv = 0.0f;
            if (ok) {
                if (mmode == 1)      mv = (float)mk_i32[idx];
                else if (mmode == 2) mv = mk_f32[idx];
                else                 mv = (float)mk_u8[idx];
            }
            m[j] = mv;
        }
#pragma unroll
        for (int dx = 0; dx < KHW; ++dx) {
            float ax = nx[dx] - cx0, ay = ny[dx] - cy0, az = nz[dx] - cz0;
            float d2a = fmaf(ax, ax, fmaf(ay, ay, az * az));
            gm0[dy*5+dx] = m[dx] * __expf(-0.5f * d2a);
            float bx = nx[dx+1] - cx1, by = ny[dx+1] - cy1, bz = nz[dx+1] - cz1;
            float d2b = fmaf(bx, bx, fmaf(by, by, bz * bz));
            gm1[dy*5+dx] = m[dx+1] * __expf(-0.5f * d2b);
        }
    }

    // ---- Phase 2: 10 groups, 4-stage ring, prefetch distance 2 (R7 structure),
    //      with the group's two channels computed interleaved for ILP. ----
    float* outp = out + ((size_t)(n * CC) * HH + h) * WWID + wa;

    for (int g = 0; g < NGROUPS; ++g) {
        if (g + 2 < NGROUPS) {
            const float* gb = sm_base + (size_t)(g + 2) * (CH_PER_G * PLANE);
            float* buf = ring + ((g + 2) & (NSTAGE - 1)) * STAGE_FLTS;
#pragma unroll
            for (int k = 0; k < SLOTS_FULL; ++k)
                cp_async16(buf + soff[k], gb + goff[k]);
            if (hasX) cp_async16(buf + soffX, gb + goffX);
            cp_commit();
            cp_wait<2>();       // group g complete; g+1, g+2 may be in flight
        } else if (g + 1 < NGROUPS) {
            cp_wait<1>();
        } else {
            cp_wait<0>();
        }
        __syncthreads();        // data visible; also fences stage reuse

        const float* B   = ring + (g & (NSTAGE - 1)) * STAGE_FLTS;
        const float* BcA = B + (cc - 2);                   // channel 0 window
        const float* BcB = B + (KHW * COLS) + (cc - 2);    // channel 1 window

        float A0e = 0.f, A0o = 0.f, A1e = 0.f, A1o = 0.f;  // px0/px1 of ch A
        float B0e = 0.f, B0o = 0.f, B1e = 0.f, B1o = 0.f;  // px0/px1 of ch B
#pragma unroll
        for (int dy = 0; dy < KHW; ++dy) {
            const float* ra = BcA + dy * COLS;
            const float* rb = BcB + dy * COLS;
            float2 a01 = *(const float2*)(ra);
            float2 b01 = *(const float2*)(rb);
            float2 a23 = *(const float2*)(ra + 2);
            float2 b23 = *(const float2*)(rb + 2);
            float2 a45 = *(const float2*)(ra + 4);
            float2 b45 = *(const float2*)(rb + 4);
            const float w0_ = gm0[dy*5+0], w1_ = gm0[dy*5+1], w2_ = gm0[dy*5+2],
                        w3_ = gm0[dy*5+3], w4_ = gm0[dy*5+4];
            const float v0_ = gm1[dy*5+0], v1_ = gm1[dy*5+1], v2_ = gm1[dy*5+2],
                        v3_ = gm1[dy*5+3], v4_ = gm1[dy*5+4];
            A0e = fmaf(w0_, a01.x, A0e);  B0e = fmaf(w0_, b01.x, B0e);
            A1e = fmaf(v0_, a01.y, A1e);  B1e = fmaf(v0_, b01.y, B1e);
            A0o = fmaf(w1_, a01.y, A0o);  B0o = fmaf(w1_, b01.y, B0o);
            A1o = fmaf(v1_, a23.x, A1o);  B1o = fmaf(v1_, b23.x, B1o);
            A0e = fmaf(w2_, a23.x, A0e);  B0e = fmaf(w2_, b23.x, B0e);
            A1e = fmaf(v2_, a23.y, A1e);  B1e = fmaf(v2_, b23.y, B1e);
            A0o = fmaf(w3_, a23.y, A0o);  B0o = fmaf(w3_, b23.y, B0o);
            A1o = fmaf(v3_, a45.x, A1o);  B1o = fmaf(v3_, b45.x, B1o);
            A0e = fmaf(w4_, a45.x, A0e);  B0e = fmaf(w4_, b45.x, B0e);
            A1e = fmaf(v4_, a45.y, A1e);  B1e = fmaf(v4_, b45.y, B1e);
        }
        const int chA = g * CH_PER_G;
        *(float2*)(outp + (size_t)(chA + 0) * PLANE) = make_float2(A0e + A0o, A1e + A1o);
        *(float2*)(outp + (size_t)(chA + 1) * PLANE) = make_float2(B0e + B0o, B1e + B1o);
        // single barrier per group: stage (g+2)%4 written above was last read
        // at iter g-2; the iter g-1 and iter g barriers separate read from write.
    }
}

extern "C" void kernel_launch(void* const* d_in, const int* in_sizes, int n_in,
                              void* d_out, int out_size)
{
    const float* xyz     = (const float*)d_in[0];
    const float* softmax = (const float*)d_in[1];
    const void*  mask    = d_in[2];
    float*       out     = (float*)d_out;

    dim3 grid(WWID / TILE, HH, NN);   // (8, 64, 4) = 2048 blocks
    dim3 block(TPB);
    lcxyz_kernel<<<grid, block>>>(xyz, softmax, mask, out);
}